// round 6
// baseline (speedup 1.0000x reference)
#include <cuda_runtime.h>
#include <math.h>

// ---------------------------------------------------------------------------
// PlaneElement fused, R6: constants in __constant__ bank (zero register
// pressure), algebraically reduced Green-Ampt, carried-diff rolling window.
// EPT=14 / TILE=3584 -> 1171 blocks = one wave at 8 blocks/SM.
// Output: [outflow_q, infil_rate_element, infil_depth_element, max_cfl]
// ---------------------------------------------------------------------------

#define BLOCK 256
#define EPT   14
#define TILE  (BLOCK * EPT)      // 3584
#define MAX_BLOCKS 8192
#define EPSF  1e-8f

struct CC {
    float cA1, cA0;    // A = max(cA1*d + cA0, 0)
    float Ka, Kb;      // fp*dt = Ka + Kb*d
    float raindt;      // rain_rate*dt  (avail = raindt + d)
    float csw, WID;    // wp = csw*A + WID   (csw = css/WID)
    float l2cman;      // log2(sqrt(SL)/MAN)
    float dtdx, inv_dt;
};

__constant__ CC g_cc;          // hot-loop constants (c-bank operands)
__device__  CC g_dc;           // staging, written by setup_kernel
__device__ float        g_psum[MAX_BLOCKS];
__device__ float        g_pmax[MAX_BLOCKS];
__device__ float        g_outflow;
__device__ unsigned int g_count = 0;

__device__ __forceinline__ float fast_lg2(float x)
{ float r; asm("lg2.approx.f32 %0, %1;" : "=f"(r) : "f"(x)); return r; }
__device__ __forceinline__ float fast_ex2(float x)
{ float r; asm("ex2.approx.f32 %0, %1;" : "=f"(r) : "f"(x)); return r; }

// ---------------------------------------------------------------------------
__global__ void setup_kernel(const float* rain_rate, const float* dt,
                             const float* theta_current, const float* F_cumulative,
                             const float* WID, const float* SS1, const float* SS2,
                             const float* MAN, const float* SL, const float* dx,
                             const float* Ks, const float* psi, const float* theta_s)
{
    float rr  = *rain_rate,  dtv = *dt,  th = *theta_current, F = *F_cumulative;
    float wid = *WID, ss1 = *SS1, ss2 = *SS2, man = *MAN, sl = *SL, dxv = *dx;
    float ks  = *Ks,  ps  = *psi, ths = *theta_s;

    CC c;
    float dtheta = fmaxf(ths - th, 0.0f);
    float F_safe = fmaxf(F, 1e-6f);
    float ksdt   = ks * dtv;
    c.Kb     = ksdt / F_safe;
    c.Ka     = ksdt + c.Kb * (ps * dtheta);
    c.raindt = rr * dtv;
    c.cA1    = (1.0f - c.Kb) * wid;
    c.cA0    = (c.raindt - c.Ka) * wid;
    c.WID    = wid;
    c.csw    = (sqrtf(1.0f + ss1 * ss1) + sqrtf(1.0f + ss2 * ss2)) / wid;
    c.l2cman = log2f(sqrtf(sl) / man);
    c.dtdx   = dtv / dxv;
    c.inv_dt = 1.0f / dtv;
    g_dc = c;
}

// p' = (max(A,EPS)/wp)^(2/3) * cman ; manning q = A * p'
__device__ __forceinline__ float manning_pc(float A)
{
    float wp = fmaf(g_cc.csw, A, g_cc.WID);
    float As = fmaxf(A, EPSF);
    float r  = __fdividef(As, wp);
    return fast_ex2(fmaf(0.66666667f, fast_lg2(r), g_cc.l2cman));
}

// A from depth: max(cA1*d + cA0, 0)
__device__ __forceinline__ float ga_Afast(float d)
{ return fmaxf(fmaf(g_cc.cA1, d, g_cc.cA0), 0.0f); }

// infiltrated depth this step (owned elements only)
__device__ __forceinline__ float ga_infil(float d)
{ return fminf(fmaf(g_cc.Kb, d, g_cc.Ka), g_cc.raindt + d); }

// minmod flux with carried diffs: a = A0 - A_left, b = A_right - A0
__device__ __forceinline__ float flux_mm(float a, float b, float A0)
{
    float m  = (fabsf(a) < fabsf(b)) ? a : b;
    float s  = (a * b > 0.0f) ? m : 0.0f;
    float Af = fmaf(0.5f, s, A0);
    return Af * manning_pc(Af);
}

__global__ void __launch_bounds__(BLOCK, 8)
fused_kernel(const float* __restrict__ depth, int N, int nblocks,
             float* __restrict__ out)
{
    // sAraw[k] = A at global index (base - 4 + k); owned g at k = g-base+4
    __shared__ __align__(16) float sAraw[TILE + 8];
    __shared__ float wsum[BLOCK / 32];
    __shared__ float wmax[BLOCK / 32];
    __shared__ int   s_last;

    const int tid  = threadIdx.x;
    const int base = blockIdx.x * TILE;
    const bool interior = (base >= 2) && (base + TILE + 2 <= N);

    float local_sum = 0.0f;
    float local_max = 0.0f;

    if (interior) {
        // ---- stage A into smem (coalesced float4), accumulate infil ----
        const float4* dp = (const float4*)(depth + base);
        float4* sA4 = (float4*)(sAraw + 4);
        #pragma unroll 1
        for (int idx = tid; idx < TILE / 4; idx += BLOCK) {
            float4 d4 = __ldg(dp + idx);
            float4 a4;
            a4.x = ga_Afast(d4.x);
            a4.y = ga_Afast(d4.y);
            a4.z = ga_Afast(d4.z);
            a4.w = ga_Afast(d4.w);
            local_sum += (ga_infil(d4.x) + ga_infil(d4.y))
                       + (ga_infil(d4.z) + ga_infil(d4.w));
            sA4[idx] = a4;
        }
        if (tid < 3) {
            int g = (tid < 2) ? (base - 2 + tid) : (base + TILE);
            sAraw[g - base + 4] = ga_Afast(__ldg(depth + g));
        }
        __syncthreads();

        // ---- rolling window with carried diff ----
        const int s0 = tid * EPT + 2;          // sAraw[s0] = A(t0-2)
        float Acur = sAraw[s0 + 1];            // A(t0-1)
        float Anxt = sAraw[s0 + 2];            // A(t0)
        float a = Acur - sAraw[s0];
        float b = Anxt - Acur;
        float flux_prev = flux_mm(a, b, Acur); // node t0-1
        #pragma unroll
        for (int i = 0; i < EPT; i++) {
            Acur = Anxt;
            Anxt = sAraw[s0 + 3 + i];
            a = b;
            b = Anxt - Acur;
            float fluxj  = flux_mm(a, b, Acur);
            float A_next = fmaxf(fmaf(-g_cc.dtdx, fluxj - flux_prev, Acur), 0.0f);
            float p      = manning_pc(A_next);
            local_max    = fmaxf(local_max, p * fminf(A_next * 1e8f, 1.0f));
            flux_prev    = fluxj;
        }
    } else {
        // ---- edge blocks (2): guarded staging + guarded window ----
        #pragma unroll 1
        for (int k = tid; k < TILE + 3; k += BLOCK) {
            int g = base - 2 + k;
            float Aval = 0.0f;
            if (g >= 0 && g < N) {
                Aval = ga_Afast(depth[g]);
                if (g >= base) local_sum += ga_infil(depth[g]);
            }
            sAraw[k + 2] = Aval;
        }
        __syncthreads();

        const int t0 = base + tid * EPT;
        float flux_prev = 0.0f;
        {
            int j = t0 - 1;
            if (j >= 0 && j < N) {
                int sj = j - base + 4;
                float A = sAraw[sj];
                float slope = 0.0f;
                if (j > 0 && j < N - 1) {
                    float a = A - sAraw[sj - 1];
                    float b = sAraw[sj + 1] - A;
                    float m = (fabsf(a) < fabsf(b)) ? a : b;
                    slope   = (a * b > 0.0f) ? m : 0.0f;
                }
                float Af = fmaf(0.5f, slope, A);
                flux_prev = Af * manning_pc(Af);
            }
        }
        #pragma unroll 1
        for (int i = 0; i < EPT; i++) {
            int g = t0 + i;
            if (g >= N) break;
            int sg = g - base + 4;
            float A = sAraw[sg];
            float slope = 0.0f;
            if (g > 0 && g < N - 1) {
                float a = A - sAraw[sg - 1];
                float b = sAraw[sg + 1] - A;
                float m = (fabsf(a) < fabsf(b)) ? a : b;
                slope   = (a * b > 0.0f) ? m : 0.0f;
            }
            float Af    = fmaf(0.5f, slope, A);
            float fluxj = Af * manning_pc(Af);
            float flux_in = (g == 0) ? 0.0f : flux_prev;
            float A_next  = fmaxf(fmaf(-g_cc.dtdx, fluxj - flux_in, A), 0.0f);
            float p       = manning_pc(A_next);
            local_max     = fmaxf(local_max, p * fminf(A_next * 1e8f, 1.0f));
            if (g == N - 1) g_outflow = A_next * p;
            flux_prev = fluxj;
        }
    }

    // ---- deterministic block reduction ----
    #pragma unroll
    for (int o = 16; o > 0; o >>= 1) {
        local_sum += __shfl_down_sync(0xffffffffu, local_sum, o);
        local_max  = fmaxf(local_max, __shfl_down_sync(0xffffffffu, local_max, o));
    }
    int warp = tid >> 5, lane = tid & 31;
    if (lane == 0) { wsum[warp] = local_sum; wmax[warp] = local_max; }
    __syncthreads();
    if (tid == 0) {
        float s = 0.0f, m = 0.0f;
        #pragma unroll
        for (int w = 0; w < BLOCK / 32; w++) {
            s += wsum[w];
            m = fmaxf(m, wmax[w]);
        }
        g_psum[blockIdx.x] = s;
        g_pmax[blockIdx.x] = m;
        __threadfence();
        unsigned int ticket = atomicAdd(&g_count, 1u);
        s_last = (ticket == (unsigned int)(nblocks - 1)) ? 1 : 0;
    }
    __syncthreads();

    // ---- last-to-finish block: fixed-order grid reduction + outputs ----
    if (s_last) {
        __threadfence();
        float s = 0.0f, m = 0.0f;
        for (int i = tid; i < nblocks; i += BLOCK) {
            s += g_psum[i];
            m  = fmaxf(m, g_pmax[i]);
        }
        #pragma unroll
        for (int o = 16; o > 0; o >>= 1) {
            s += __shfl_down_sync(0xffffffffu, s, o);
            m  = fmaxf(m, __shfl_down_sync(0xffffffffu, m, o));
        }
        if (lane == 0) { wsum[warp] = s; wmax[warp] = m; }
        __syncthreads();
        if (tid == 0) {
            float st = 0.0f, mt = 0.0f;
            #pragma unroll
            for (int w = 0; w < BLOCK / 32; w++) {
                st += wsum[w];
                mt  = fmaxf(mt, wmax[w]);
            }
            float mean_depth = st / (float)N;
            out[0] = g_outflow;
            out[1] = mean_depth * g_cc.inv_dt;
            out[2] = mean_depth;
            out[3] = mt * g_cc.dtdx;
            g_count = 0;   // reset for next graph replay
        }
    }
}

// ---------------------------------------------------------------------------
extern "C" void kernel_launch(void* const* d_in, const int* in_sizes, int n_in,
                              void* d_out, int out_size)
{
    const float* depth = (const float*)d_in[0];
    const int N = in_sizes[0];
    int nblocks = (N + TILE - 1) / TILE;   // N=2^22 -> 1171 blocks (one wave)
    if (nblocks > MAX_BLOCKS) nblocks = MAX_BLOCKS;

    setup_kernel<<<1, 1>>>(
        (const float*)d_in[1],  (const float*)d_in[2],  (const float*)d_in[4],
        (const float*)d_in[5],  (const float*)d_in[6],  (const float*)d_in[7],
        (const float*)d_in[8],  (const float*)d_in[9],  (const float*)d_in[10],
        (const float*)d_in[11], (const float*)d_in[12], (const float*)d_in[13],
        (const float*)d_in[14]);

    // Stage -> constant bank (device-to-device async copy, graph-capturable)
    void* src = nullptr;
    cudaGetSymbolAddress(&src, g_dc);
    cudaMemcpyToSymbolAsync(g_cc, src, sizeof(CC), 0, cudaMemcpyDeviceToDevice);

    fused_kernel<<<nblocks, BLOCK>>>(depth, N, nblocks, (float*)d_out);
}

// round 7
// speedup vs baseline: 1.1250x; 1.1250x over previous
#include <cuda_runtime.h>
#include <math.h>

// ---------------------------------------------------------------------------
// PlaneElement fused, R7: monotone-velocity trick (max_cfl = vel(max A_next),
// so only ONE manning per element), __constant__ bank consts, parallel-load
// setup kernel. EPT=14/TILE=3584 -> 1171 blocks = one wave at 8 blocks/SM.
// Output: [outflow_q, infil_rate_element, infil_depth_element, max_cfl]
// ---------------------------------------------------------------------------

#define BLOCK 256
#define EPT   14
#define TILE  (BLOCK * EPT)      // 3584
#define MAX_BLOCKS 8192
#define EPSF  1e-8f

struct CC {
    float cA1, cA0;    // A = max(cA1*d + cA0, 0)
    float Ka, Kb;      // fp*dt = Ka + Kb*d
    float raindt;      // avail = raindt + d
    float csw, WID;    // wp = csw*A + WID
    float l2cman;      // log2(sqrt(SL)/MAN)
    float dtdx, inv_dt;
};

__constant__ CC g_cc;
__device__  CC g_dc;
__device__ float        g_psum[MAX_BLOCKS];
__device__ float        g_pmax[MAX_BLOCKS];   // per-block max A_next
__device__ float        g_outflow;
__device__ unsigned int g_count = 0;

__device__ __forceinline__ float fast_lg2(float x)
{ float r; asm("lg2.approx.f32 %0, %1;" : "=f"(r) : "f"(x)); return r; }
__device__ __forceinline__ float fast_ex2(float x)
{ float r; asm("ex2.approx.f32 %0, %1;" : "=f"(r) : "f"(x)); return r; }

// ---------------------------------------------------------------------------
__global__ void setup_kernel(const float* rain_rate, const float* dt,
                             const float* theta_current, const float* F_cumulative,
                             const float* WID, const float* SS1, const float* SS2,
                             const float* MAN, const float* SL, const float* dx,
                             const float* Ks, const float* psi, const float* theta_s)
{
    __shared__ float v[13];
    const float* ptrs[13] = { rain_rate, dt, theta_current, F_cumulative, WID,
                              SS1, SS2, MAN, SL, dx, Ks, psi, theta_s };
    int t = threadIdx.x;
    if (t < 13) v[t] = __ldg(ptrs[t]);      // 13 parallel loads
    __syncthreads();
    if (t == 0) {
        float rr = v[0], dtv = v[1], th = v[2], F = v[3], wid = v[4];
        float ss1 = v[5], ss2 = v[6], man = v[7], sl = v[8], dxv = v[9];
        float ks = v[10], ps = v[11], ths = v[12];
        CC c;
        float dtheta = fmaxf(ths - th, 0.0f);
        float F_safe = fmaxf(F, 1e-6f);
        float ksdt   = ks * dtv;
        c.Kb     = ksdt / F_safe;
        c.Ka     = ksdt + c.Kb * (ps * dtheta);
        c.raindt = rr * dtv;
        c.cA1    = (1.0f - c.Kb) * wid;
        c.cA0    = (c.raindt - c.Ka) * wid;
        c.WID    = wid;
        c.csw    = (sqrtf(1.0f + ss1 * ss1) + sqrtf(1.0f + ss2 * ss2)) / wid;
        c.l2cman = log2f(sqrtf(sl) / man);
        c.dtdx   = dtv / dxv;
        c.inv_dt = 1.0f / dtv;
        g_dc = c;
    }
}

// p' = (max(A,EPS)/wp)^(2/3) * cman ; manning q = A * p'
__device__ __forceinline__ float manning_pc(float A)
{
    float wp = fmaf(g_cc.csw, A, g_cc.WID);
    float As = fmaxf(A, EPSF);
    float r  = __fdividef(As, wp);
    return fast_ex2(fmaf(0.66666667f, fast_lg2(r), g_cc.l2cman));
}

__device__ __forceinline__ float ga_Afast(float d)
{ return fmaxf(fmaf(g_cc.cA1, d, g_cc.cA0), 0.0f); }

__device__ __forceinline__ float ga_infil(float d)
{ return fminf(fmaf(g_cc.Kb, d, g_cc.Ka), g_cc.raindt + d); }

// minmod flux with carried diffs: a = A0 - A_left, b = A_right - A0
__device__ __forceinline__ float flux_mm(float a, float b, float A0)
{
    float m  = (fabsf(a) < fabsf(b)) ? a : b;
    float s  = (a * b > 0.0f) ? m : 0.0f;
    float Af = fmaf(0.5f, s, A0);
    return Af * manning_pc(Af);
}

__global__ void __launch_bounds__(BLOCK, 8)
fused_kernel(const float* __restrict__ depth, int N, int nblocks,
             float* __restrict__ out)
{
    __shared__ __align__(16) float sAraw[TILE + 8];
    __shared__ float wsum[BLOCK / 32];
    __shared__ float wmax[BLOCK / 32];
    __shared__ int   s_last;

    const int tid  = threadIdx.x;
    const int base = blockIdx.x * TILE;
    const bool interior = (base >= 2) && (base + TILE + 2 <= N);

    float local_sum = 0.0f;
    float local_maxA = 0.0f;    // max A_next (vel is monotone in A_next)

    if (interior) {
        // ---- stage A into smem (coalesced float4), accumulate infil ----
        const float4* dp = (const float4*)(depth + base);
        float4* sA4 = (float4*)(sAraw + 4);
        #pragma unroll 1
        for (int idx = tid; idx < TILE / 4; idx += BLOCK) {
            float4 d4 = __ldg(dp + idx);
            float4 a4;
            a4.x = ga_Afast(d4.x);
            a4.y = ga_Afast(d4.y);
            a4.z = ga_Afast(d4.z);
            a4.w = ga_Afast(d4.w);
            local_sum += (ga_infil(d4.x) + ga_infil(d4.y))
                       + (ga_infil(d4.z) + ga_infil(d4.w));
            sA4[idx] = a4;
        }
        if (tid < 3) {
            int g = (tid < 2) ? (base - 2 + tid) : (base + TILE);
            sAraw[g - base + 4] = ga_Afast(__ldg(depth + g));
        }
        __syncthreads();

        // ---- rolling window, carried diff; reduce max A_next only ----
        const int s0 = tid * EPT + 2;          // sAraw[s0] = A(t0-2)
        float Acur = sAraw[s0 + 1];
        float Anxt = sAraw[s0 + 2];
        float a = Acur - sAraw[s0];
        float b = Anxt - Acur;
        float flux_prev = flux_mm(a, b, Acur); // node t0-1
        #pragma unroll
        for (int i = 0; i < EPT; i++) {
            Acur = Anxt;
            Anxt = sAraw[s0 + 3 + i];
            a = b;
            b = Anxt - Acur;
            float fluxj  = flux_mm(a, b, Acur);
            float A_next = fmaxf(fmaf(-g_cc.dtdx, fluxj - flux_prev, Acur), 0.0f);
            local_maxA   = fmaxf(local_maxA, A_next);
            flux_prev    = fluxj;
        }
    } else {
        // ---- edge blocks (2): guarded staging + guarded window ----
        #pragma unroll 1
        for (int k = tid; k < TILE + 3; k += BLOCK) {
            int g = base - 2 + k;
            float Aval = 0.0f;
            if (g >= 0 && g < N) {
                Aval = ga_Afast(depth[g]);
                if (g >= base) local_sum += ga_infil(depth[g]);
            }
            sAraw[k + 2] = Aval;
        }
        __syncthreads();

        const int t0 = base + tid * EPT;
        float flux_prev = 0.0f;
        {
            int j = t0 - 1;
            if (j >= 0 && j < N) {
                int sj = j - base + 4;
                float A = sAraw[sj];
                float slope = 0.0f;
                if (j > 0 && j < N - 1) {
                    float a = A - sAraw[sj - 1];
                    float b = sAraw[sj + 1] - A;
                    float m = (fabsf(a) < fabsf(b)) ? a : b;
                    slope   = (a * b > 0.0f) ? m : 0.0f;
                }
                float Af = fmaf(0.5f, slope, A);
                flux_prev = Af * manning_pc(Af);
            }
        }
        #pragma unroll 1
        for (int i = 0; i < EPT; i++) {
            int g = t0 + i;
            if (g >= N) break;
            int sg = g - base + 4;
            float A = sAraw[sg];
            float slope = 0.0f;
            if (g > 0 && g < N - 1) {
                float a = A - sAraw[sg - 1];
                float b = sAraw[sg + 1] - A;
                float m = (fabsf(a) < fabsf(b)) ? a : b;
                slope   = (a * b > 0.0f) ? m : 0.0f;
            }
            float Af    = fmaf(0.5f, slope, A);
            float fluxj = Af * manning_pc(Af);
            float flux_in = (g == 0) ? 0.0f : flux_prev;
            float A_next  = fmaxf(fmaf(-g_cc.dtdx, fluxj - flux_in, A), 0.0f);
            local_maxA    = fmaxf(local_maxA, A_next);
            if (g == N - 1) g_outflow = A_next * manning_pc(A_next);
            flux_prev = fluxj;
        }
    }

    // ---- deterministic block reduction (sum infil, max A_next) ----
    #pragma unroll
    for (int o = 16; o > 0; o >>= 1) {
        local_sum  += __shfl_down_sync(0xffffffffu, local_sum, o);
        local_maxA  = fmaxf(local_maxA, __shfl_down_sync(0xffffffffu, local_maxA, o));
    }
    int warp = tid >> 5, lane = tid & 31;
    if (lane == 0) { wsum[warp] = local_sum; wmax[warp] = local_maxA; }
    __syncthreads();
    if (tid == 0) {
        float s = 0.0f, m = 0.0f;
        #pragma unroll
        for (int w = 0; w < BLOCK / 32; w++) {
            s += wsum[w];
            m = fmaxf(m, wmax[w]);
        }
        g_psum[blockIdx.x] = s;
        g_pmax[blockIdx.x] = m;
        __threadfence();
        unsigned int ticket = atomicAdd(&g_count, 1u);
        s_last = (ticket == (unsigned int)(nblocks - 1)) ? 1 : 0;
    }
    __syncthreads();

    // ---- last block: fixed-order grid reduction, single vel eval ----
    if (s_last) {
        __threadfence();
        float s = 0.0f, m = 0.0f;
        for (int i = tid; i < nblocks; i += BLOCK) {
            s += g_psum[i];
            m  = fmaxf(m, g_pmax[i]);
        }
        #pragma unroll
        for (int o = 16; o > 0; o >>= 1) {
            s += __shfl_down_sync(0xffffffffu, s, o);
            m  = fmaxf(m, __shfl_down_sync(0xffffffffu, m, o));
        }
        if (lane == 0) { wsum[warp] = s; wmax[warp] = m; }
        __syncthreads();
        if (tid == 0) {
            float st = 0.0f, mA = 0.0f;
            #pragma unroll
            for (int w = 0; w < BLOCK / 32; w++) {
                st += wsum[w];
                mA  = fmaxf(mA, wmax[w]);
            }
            // vel(A) = p(A) * min(A*1e8, 1) is monotone in A -> evaluate once
            float vel = manning_pc(mA) * fminf(mA * 1e8f, 1.0f);
            float mean_depth = st / (float)N;
            out[0] = g_outflow;
            out[1] = mean_depth * g_cc.inv_dt;
            out[2] = mean_depth;
            out[3] = vel * g_cc.dtdx;
            g_count = 0;   // reset for next graph replay
        }
    }
}

// ---------------------------------------------------------------------------
extern "C" void kernel_launch(void* const* d_in, const int* in_sizes, int n_in,
                              void* d_out, int out_size)
{
    const float* depth = (const float*)d_in[0];
    const int N = in_sizes[0];
    int nblocks = (N + TILE - 1) / TILE;   // N=2^22 -> 1171 blocks (one wave)
    if (nblocks > MAX_BLOCKS) nblocks = MAX_BLOCKS;

    setup_kernel<<<1, 32>>>(
        (const float*)d_in[1],  (const float*)d_in[2],  (const float*)d_in[4],
        (const float*)d_in[5],  (const float*)d_in[6],  (const float*)d_in[7],
        (const float*)d_in[8],  (const float*)d_in[9],  (const float*)d_in[10],
        (const float*)d_in[11], (const float*)d_in[12], (const float*)d_in[13],
        (const float*)d_in[14]);

    void* src = nullptr;
    cudaGetSymbolAddress(&src, g_dc);
    cudaMemcpyToSymbolAsync(g_cc, src, sizeof(CC), 0, cudaMemcpyDeviceToDevice);

    fused_kernel<<<nblocks, BLOCK>>>(depth, N, nblocks, (float*)d_out);
}